// round 11
// baseline (speedup 1.0000x reference)
#include <cuda_runtime.h>
#include <cuda_fp16.h>
#include <math.h>
#include <stdint.h>

// Problem constants
#define BATCH   32
#define SEQ     512
#define DIM     1024
#define FFN     2048
#define GDOM    4
#define NTOK    (BATCH * SEQ)
#define LN_EPS  1e-6f

// GEMM tiling: 128x128 CTA, BK=64 halves, 256 threads (8 warps, 2m x 4n)
#define BM 128
#define BN 128
#define BKK 64
#define NSTG 3
#define PADH 72                               // halves per k-row (64 data + 8 pad)
#define STAGE_H ((BM + BN) * PADH)            // 18432 halves = 36864 B per stage
#define SMEM_BYTES (NSTG * STAGE_H * 2)       // 110592

// ---------------------------------------------------------------------------
// Scratch (device globals; allocation-free per harness rules)
// ---------------------------------------------------------------------------
__device__ __half g_ln [(size_t)NTOK * DIM];        // 32 MB LN output (fp16)
__device__ __half g_h  [(size_t)NTOK * FFN];        // 64 MB hidden (fp16)
__device__ __half g_w1t[(size_t)GDOM * FFN * DIM];  // 16 MB W1^T [g][F][D]
__device__ __half g_w2t[(size_t)GDOM * DIM * FFN];  // 16 MB W2^T [g][D][F]
__device__ int    g_dom[BATCH];

// ---------------------------------------------------------------------------
// PTX helpers
// ---------------------------------------------------------------------------
__device__ __forceinline__ uint32_t smem_u32(const void* p) {
    uint32_t a;
    asm("{ .reg .u64 t; cvta.to.shared.u64 t, %1; cvt.u32.u64 %0, t; }"
        : "=r"(a) : "l"(p));
    return a;
}
__device__ __forceinline__ void cp_async16(void* s, const void* g) {
    uint32_t sa = smem_u32(s);
    asm volatile("cp.async.cg.shared.global [%0], [%1], 16;" :: "r"(sa), "l"(g));
}
#define CP_COMMIT() asm volatile("cp.async.commit_group;" ::: "memory")
#define CP_WAIT(n)  asm volatile("cp.async.wait_group %0;" :: "n"(n) : "memory")

__device__ __forceinline__ void ldsm_x4(uint32_t& r0, uint32_t& r1,
                                        uint32_t& r2, uint32_t& r3,
                                        uint32_t addr) {
    asm volatile("ldmatrix.sync.aligned.m8n8.x4.shared.b16 {%0,%1,%2,%3}, [%4];"
                 : "=r"(r0), "=r"(r1), "=r"(r2), "=r"(r3) : "r"(addr));
}

__device__ __forceinline__ void mma_f16(float* c, const uint32_t* a,
                                        const uint32_t* b) {
    asm volatile(
        "mma.sync.aligned.m16n8k16.row.col.f32.f16.f16.f32 "
        "{%0,%1,%2,%3}, {%4,%5,%6,%7}, {%8,%9}, {%0,%1,%2,%3};"
        : "+f"(c[0]), "+f"(c[1]), "+f"(c[2]), "+f"(c[3])
        : "r"(a[0]), "r"(a[1]), "r"(a[2]), "r"(a[3]), "r"(b[0]), "r"(b[1]));
}

// ---------------------------------------------------------------------------
// K0: batch -> domain
// ---------------------------------------------------------------------------
__global__ void dom_kernel(const int* __restrict__ idx) {
    int i = threadIdx.x;
    if (i < BATCH) g_dom[idx[i]] = i >> 3;
}

// ---------------------------------------------------------------------------
// K1 (fused prep): W1 transpose | W2 transpose | LayerNorm, role by blockIdx.
// ---------------------------------------------------------------------------
#define T_W1   (GDOM * (DIM / 32) * (FFN / 32))    // 8192
#define T_W2   (GDOM * (FFN / 32) * (DIM / 32))    // 8192
#define PREP_GRID (T_W1 + T_W2 + NTOK)             // 32768

__global__ __launch_bounds__(256)
void prep_kernel(const float* __restrict__ W1, const float* __restrict__ W2,
                 const float* __restrict__ x, const float* __restrict__ G,
                 const float* __restrict__ Bn) {
    __shared__ float tbuf[32][33];
    __shared__ float red_s[8], red_ss[8];
    __shared__ float s_mu, s_inv;

    const int bid = blockIdx.x;
    const int tid = threadIdx.x;

    if (bid < T_W1 + T_W2) {
        const bool isw1 = bid < T_W1;
        const int id  = isw1 ? bid : bid - T_W1;
        const int R   = isw1 ? DIM : FFN;
        const int C   = isw1 ? FFN : DIM;
        const int ctiles = C / 32;
        const int g   = id / ((R / 32) * ctiles);
        const int rem = id % ((R / 32) * ctiles);
        const int cy  = rem / ctiles;
        const int cx  = rem % ctiles;
        const float* Wg  = (isw1 ? W1 : W2) + (size_t)g * R * C;
        __half*      Wtg = (isw1 ? g_w1t : g_w2t) + (size_t)g * R * C;
        const int r0 = cy * 32, c0 = cx * 32;
        const int tx = tid & 31, ty = tid >> 5;
        #pragma unroll
        for (int i = 0; i < 32; i += 8)
            tbuf[ty + i][tx] = Wg[(size_t)(r0 + ty + i) * C + c0 + tx];
        __syncthreads();
        #pragma unroll
        for (int i = 0; i < 32; i += 8)
            Wtg[(size_t)(c0 + ty + i) * R + r0 + tx] =
                __float2half_rn(tbuf[tx][ty + i]);
        return;
    }

    const int r = bid - (T_W1 + T_W2);
    const int g = g_dom[r >> 9];

    const float4 v = ((const float4*)(x + (size_t)r * DIM))[tid];
    float s  = v.x + v.y + v.z + v.w;
    float ss = v.x * v.x + v.y * v.y + v.z * v.z + v.w * v.w;
    #pragma unroll
    for (int o = 16; o > 0; o >>= 1) {
        s  += __shfl_down_sync(0xffffffffu, s,  o);
        ss += __shfl_down_sync(0xffffffffu, ss, o);
    }
    if ((tid & 31) == 0) { red_s[tid >> 5] = s; red_ss[tid >> 5] = ss; }
    __syncthreads();
    if (tid == 0) {
        float ts = 0.f, tss = 0.f;
        #pragma unroll
        for (int i = 0; i < 8; i++) { ts += red_s[i]; tss += red_ss[i]; }
        float mu  = ts * (1.0f / DIM);
        float var = (tss - (float)DIM * mu * mu) * (1.0f / (DIM - 1));
        var = fmaxf(var, 0.0f);
        s_mu  = mu;
        s_inv = 1.0f / (sqrtf(var) + LN_EPS);
    }
    __syncthreads();
    const float mu = s_mu, inv = s_inv;
    const float4 gv = ((const float4*)(G  + (size_t)g * DIM))[tid];
    const float4 bv = ((const float4*)(Bn + (size_t)g * DIM))[tid];
    float2 y0, y1;
    y0.x = gv.x * (v.x - mu) * inv + bv.x;
    y0.y = gv.y * (v.y - mu) * inv + bv.y;
    y1.x = gv.z * (v.z - mu) * inv + bv.z;
    y1.y = gv.w * (v.w - mu) * inv + bv.w;
    __half2* dst = (__half2*)(g_ln + (size_t)r * DIM);
    dst[tid * 2 + 0] = __float22half2_rn(y0);
    dst[tid * 2 + 1] = __float22half2_rn(y1);
}

// ---------------------------------------------------------------------------
// K2/K3: fp16 mma.sync grouped GEMM, 128x128 tile, 256 threads, BK=64.
// Decoupled pipeline: CP_WAIT(1) at top of body guarantees only stage kt
// (newest group may remain in flight), giving each stage load ~2 bodies of
// compute to land. One exposed LDSM (slice 0) per body.
// ---------------------------------------------------------------------------
template<bool RELU, bool RESID, bool OUT_HALF>
__global__ __launch_bounds__(256, 2)
void mma_gemm(const __half* __restrict__ A, const __half* __restrict__ Bt,
              const float* __restrict__ bias, const float* __restrict__ resid,
              void* __restrict__ Cv, int N, int K) {
    extern __shared__ __half sm[];
    const int tid  = threadIdx.x;
    const int row0 = blockIdx.y * BM;
    const int col0 = blockIdx.x * BN;
    const int g    = g_dom[row0 >> 9];
    const __half* Bg = Bt + (size_t)g * N * K;

    const int lane  = tid & 31;
    const int wid   = tid >> 5;
    const int gid   = lane >> 2;
    const int tg    = lane & 3;
    const int warpm = wid & 1;        // m offset *64
    const int warpn = wid >> 1;       // n offset *32

    const uint32_t sm_base = smem_u32(sm);

    // ldmatrix lane offsets (bytes, relative to stage base); PADH=72 rows
    // (144 B) -> 8-row matrix hits 16*r mod 128 slots, conflict-free.
    const uint32_t aoff_b =
        (uint32_t)((warpm * 64 + (lane & 7) + ((lane >> 3) & 1) * 8) * PADH
                   + (lane >> 4) * 8) * 2u;
    const uint32_t boff_b =
        (uint32_t)(BM * PADH) * 2u +
        (uint32_t)((warpn * 32 + (lane & 7) + (lane >> 4) * 8) * PADH
                   + ((lane >> 3) & 1) * 8) * 2u;

    // stage loader: A and B each 128 rows x 8 16B-chunks = 1024 chunks,
    // 4 per thread per operand
    auto load_stage = [&](int kt, int s) {
        const int k0 = kt * BKK;
        __half* As = sm + s * STAGE_H;
        __half* Bs = As + BM * PADH;
        #pragma unroll
        for (int j = 0; j < 4; j++) {
            int c = tid + j * 256;
            int m = c >> 3, kc = (c & 7) << 3;
            cp_async16(&As[m * PADH + kc],
                       A + (size_t)(row0 + m) * K + k0 + kc);
        }
        #pragma unroll
        for (int j = 0; j < 4; j++) {
            int c = tid + j * 256;
            int n = c >> 3, kc = (c & 7) << 3;
            cp_async16(&Bs[n * PADH + kc],
                       Bg + (size_t)(col0 + n) * K + k0 + kc);
        }
        CP_COMMIT();
    };

    // fragment load for one k16 slice (ks in {0..3}) of stage at byte base
    auto frag_load = [&](uint32_t base, int ks, uint32_t a[4][4],
                         uint32_t b[4][2]) {
        const uint32_t Aaddr = base + aoff_b + (uint32_t)ks * 32u;
        const uint32_t Baddr = base + boff_b + (uint32_t)ks * 32u;
        #pragma unroll
        for (int mf = 0; mf < 4; mf++)
            ldsm_x4(a[mf][0], a[mf][1], a[mf][2], a[mf][3],
                    Aaddr + (uint32_t)(mf * 16 * PADH) * 2u);
        ldsm_x4(b[0][0], b[0][1], b[1][0], b[1][1], Baddr);
        ldsm_x4(b[2][0], b[2][1], b[3][0], b[3][1],
                Baddr + (uint32_t)(16 * PADH) * 2u);
    };

    float acc[4][4][4];
    #pragma unroll
    for (int i = 0; i < 4; i++)
        #pragma unroll
        for (int j = 0; j < 4; j++)
            #pragma unroll
            for (int q = 0; q < 4; q++) acc[i][j][q] = 0.f;

    const int KT = K / BKK;

    // prologue: issue stages 0,1 into slots 0,1 (no drain here)
    load_stage(0, 0);
    load_stage(1, 1);

    uint32_t a[2][4][4], b[2][4][2];
    int s_cur = 0;                 // slot of stage kt
    int s_ld  = NSTG - 1;          // slot for stage kt+2

    for (int kt = 0; kt < KT; kt++) {
        // stage kt resident (all groups except the newest complete);
        // barrier also retires stage kt-1's readers before its slot reuse
        CP_WAIT(1);
        __syncthreads();
        {
            int nx = kt + NSTG - 1;
            if (nx < KT) load_stage(nx, s_ld);
            if (++s_ld == NSTG) s_ld = 0;
        }
        const uint32_t base_cur = sm_base + (uint32_t)(s_cur * STAGE_H) * 2u;
        if (++s_cur == NSTG) s_cur = 0;

        // slice 0 fragments (one exposed LDSM per body), then ping-pong
        frag_load(base_cur, 0, a[0], b[0]);
        #pragma unroll
        for (int ks = 0; ks < 4; ks++) {
            const int cb = ks & 1, nb = cb ^ 1;
            if (ks < 3)
                frag_load(base_cur, ks + 1, a[nb], b[nb]);
            #pragma unroll
            for (int mf = 0; mf < 4; mf++)
                #pragma unroll
                for (int nf = 0; nf < 4; nf++)
                    mma_f16(acc[mf][nf], a[cb][mf], b[cb][nf]);
        }
    }

    // epilogue
    const float* biasg = bias + (size_t)g * N;
    #pragma unroll
    for (int mf = 0; mf < 4; mf++) {
        #pragma unroll
        for (int h = 0; h < 2; h++) {
            const int r = row0 + warpm * 64 + mf * 16 + gid + h * 8;
            const float* rrow = RESID ? (resid + (size_t)r * N) : nullptr;
            #pragma unroll
            for (int nf = 0; nf < 4; nf++) {
                const int cidx = col0 + warpn * 32 + nf * 8 + tg * 2;
                float2 v;
                v.x = acc[mf][nf][h * 2 + 0] + biasg[cidx];
                v.y = acc[mf][nf][h * 2 + 1] + biasg[cidx + 1];
                if (RELU) { v.x = fmaxf(v.x, 0.f); v.y = fmaxf(v.y, 0.f); }
                if (RESID) { v.x += rrow[cidx]; v.y += rrow[cidx + 1]; }
                if (OUT_HALF) {
                    __half2* crow = (__half2*)((__half*)Cv + (size_t)r * N + cidx);
                    *crow = __float22half2_rn(v);
                } else {
                    *(float2*)((float*)Cv + (size_t)r * N + cidx) = v;
                }
            }
        }
    }
}

// ---------------------------------------------------------------------------
extern "C" void kernel_launch(void* const* d_in, const int* in_sizes, int n_in,
                              void* d_out, int out_size) {
    const float* x   = (const float*)d_in[0];
    const int*   idx = (const int*)  d_in[1];
    const float* W1  = (const float*)d_in[2];
    const float* B1  = (const float*)d_in[3];
    const float* W2  = (const float*)d_in[4];
    const float* B2  = (const float*)d_in[5];
    const float* G   = (const float*)d_in[6];
    const float* Bn  = (const float*)d_in[7];
    float*       out = (float*)d_out;

    __half *ln_ptr, *h_ptr, *w1t_ptr, *w2t_ptr;
    cudaGetSymbolAddress((void**)&ln_ptr,  g_ln);
    cudaGetSymbolAddress((void**)&h_ptr,   g_h);
    cudaGetSymbolAddress((void**)&w1t_ptr, g_w1t);
    cudaGetSymbolAddress((void**)&w2t_ptr, g_w2t);

    static bool attr_done = false;
    if (!attr_done) {
        cudaFuncSetAttribute(mma_gemm<true, false, true>,
                             cudaFuncAttributeMaxDynamicSharedMemorySize, SMEM_BYTES);
        cudaFuncSetAttribute(mma_gemm<false, true, false>,
                             cudaFuncAttributeMaxDynamicSharedMemorySize, SMEM_BYTES);
        attr_done = true;
    }

    dom_kernel<<<1, 32>>>(idx);

    // fused: W1^T, W2^T, layernorm
    prep_kernel<<<PREP_GRID, 256>>>(W1, W2, x, G, Bn);

    // gemm1: h = relu(ln @ W1[g] + B1[g]) -> fp16   (KT = 16)
    mma_gemm<true, false, true><<<dim3(FFN / BN, NTOK / BM), 256, SMEM_BYTES>>>(
        ln_ptr, w1t_ptr, B1, nullptr, h_ptr, FFN, DIM);

    // gemm2: out = x + h @ W2[g] + B2[g] -> fp32    (KT = 32)
    mma_gemm<false, true, false><<<dim3(DIM / BN, NTOK / BM), 256, SMEM_BYTES>>>(
        h_ptr, w2t_ptr, B2, x, out, DIM, FFN);
}

// round 12
// speedup vs baseline: 1.0925x; 1.0925x over previous
#include <cuda_runtime.h>
#include <cuda_fp16.h>
#include <math.h>
#include <stdint.h>

// Problem constants
#define BATCH   32
#define SEQ     512
#define DIM     1024
#define FFN     2048
#define GDOM    4
#define NTOK    (BATCH * SEQ)
#define LN_EPS  1e-6f

// GEMM tiling: 128x128 CTA, BK=64 halves, 256 threads (8 warps, 2m x 4n)
#define BM 128
#define BN 128
#define BKK 64
#define NSTG 3
#define PADH 72                               // halves per k-row (64 data + 8 pad)
#define STAGE_H ((BM + BN) * PADH)            // 18432 halves = 36864 B per stage
#define SMEM_BYTES (NSTG * STAGE_H * 2)       // 110592

// ---------------------------------------------------------------------------
// Scratch (device globals; allocation-free per harness rules)
// ---------------------------------------------------------------------------
__device__ __half g_ln [(size_t)NTOK * DIM];        // 32 MB LN output (fp16)
__device__ __half g_h  [(size_t)NTOK * FFN];        // 64 MB hidden (fp16)
__device__ __half g_w1t[(size_t)GDOM * FFN * DIM];  // 16 MB W1^T [g][F][D]
__device__ __half g_w2t[(size_t)GDOM * DIM * FFN];  // 16 MB W2^T [g][D][F]
__device__ int    g_dom[BATCH];

// ---------------------------------------------------------------------------
// PTX helpers
// ---------------------------------------------------------------------------
__device__ __forceinline__ uint32_t smem_u32(const void* p) {
    uint32_t a;
    asm("{ .reg .u64 t; cvta.to.shared.u64 t, %1; cvt.u32.u64 %0, t; }"
        : "=r"(a) : "l"(p));
    return a;
}
__device__ __forceinline__ void cp_async16(void* s, const void* g) {
    uint32_t sa = smem_u32(s);
    asm volatile("cp.async.cg.shared.global [%0], [%1], 16;" :: "r"(sa), "l"(g));
}
#define CP_COMMIT() asm volatile("cp.async.commit_group;" ::: "memory")
#define CP_WAIT(n)  asm volatile("cp.async.wait_group %0;" :: "n"(n) : "memory")

__device__ __forceinline__ void ldsm_x4(uint32_t& r0, uint32_t& r1,
                                        uint32_t& r2, uint32_t& r3,
                                        uint32_t addr) {
    asm volatile("ldmatrix.sync.aligned.m8n8.x4.shared.b16 {%0,%1,%2,%3}, [%4];"
                 : "=r"(r0), "=r"(r1), "=r"(r2), "=r"(r3) : "r"(addr));
}

__device__ __forceinline__ void mma_f16(float* c, const uint32_t* a,
                                        const uint32_t* b) {
    asm volatile(
        "mma.sync.aligned.m16n8k16.row.col.f32.f16.f16.f32 "
        "{%0,%1,%2,%3}, {%4,%5,%6,%7}, {%8,%9}, {%0,%1,%2,%3};"
        : "+f"(c[0]), "+f"(c[1]), "+f"(c[2]), "+f"(c[3])
        : "r"(a[0]), "r"(a[1]), "r"(a[2]), "r"(a[3]), "r"(b[0]), "r"(b[1]));
}

// ---------------------------------------------------------------------------
// K0: batch -> domain
// ---------------------------------------------------------------------------
__global__ void dom_kernel(const int* __restrict__ idx) {
    int i = threadIdx.x;
    if (i < BATCH) g_dom[idx[i]] = i >> 3;
}

// ---------------------------------------------------------------------------
// K1 (fused prep): W1 transpose | W2 transpose | LayerNorm, role by blockIdx.
// ---------------------------------------------------------------------------
#define T_W1   (GDOM * (DIM / 32) * (FFN / 32))    // 8192
#define T_W2   (GDOM * (FFN / 32) * (DIM / 32))    // 8192
#define PREP_GRID (T_W1 + T_W2 + NTOK)             // 32768

__global__ __launch_bounds__(256)
void prep_kernel(const float* __restrict__ W1, const float* __restrict__ W2,
                 const float* __restrict__ x, const float* __restrict__ G,
                 const float* __restrict__ Bn) {
    __shared__ float tbuf[32][33];
    __shared__ float red_s[8], red_ss[8];
    __shared__ float s_mu, s_inv;

    const int bid = blockIdx.x;
    const int tid = threadIdx.x;

    if (bid < T_W1 + T_W2) {
        const bool isw1 = bid < T_W1;
        const int id  = isw1 ? bid : bid - T_W1;
        const int R   = isw1 ? DIM : FFN;
        const int C   = isw1 ? FFN : DIM;
        const int ctiles = C / 32;
        const int g   = id / ((R / 32) * ctiles);
        const int rem = id % ((R / 32) * ctiles);
        const int cy  = rem / ctiles;
        const int cx  = rem % ctiles;
        const float* Wg  = (isw1 ? W1 : W2) + (size_t)g * R * C;
        __half*      Wtg = (isw1 ? g_w1t : g_w2t) + (size_t)g * R * C;
        const int r0 = cy * 32, c0 = cx * 32;
        const int tx = tid & 31, ty = tid >> 5;
        #pragma unroll
        for (int i = 0; i < 32; i += 8)
            tbuf[ty + i][tx] = Wg[(size_t)(r0 + ty + i) * C + c0 + tx];
        __syncthreads();
        #pragma unroll
        for (int i = 0; i < 32; i += 8)
            Wtg[(size_t)(c0 + ty + i) * R + r0 + tx] =
                __float2half_rn(tbuf[tx][ty + i]);
        return;
    }

    const int r = bid - (T_W1 + T_W2);
    const int g = g_dom[r >> 9];

    const float4 v = ((const float4*)(x + (size_t)r * DIM))[tid];
    float s  = v.x + v.y + v.z + v.w;
    float ss = v.x * v.x + v.y * v.y + v.z * v.z + v.w * v.w;
    #pragma unroll
    for (int o = 16; o > 0; o >>= 1) {
        s  += __shfl_down_sync(0xffffffffu, s,  o);
        ss += __shfl_down_sync(0xffffffffu, ss, o);
    }
    if ((tid & 31) == 0) { red_s[tid >> 5] = s; red_ss[tid >> 5] = ss; }
    __syncthreads();
    if (tid == 0) {
        float ts = 0.f, tss = 0.f;
        #pragma unroll
        for (int i = 0; i < 8; i++) { ts += red_s[i]; tss += red_ss[i]; }
        float mu  = ts * (1.0f / DIM);
        float var = (tss - (float)DIM * mu * mu) * (1.0f / (DIM - 1));
        var = fmaxf(var, 0.0f);
        s_mu  = mu;
        s_inv = 1.0f / (sqrtf(var) + LN_EPS);
    }
    __syncthreads();
    const float mu = s_mu, inv = s_inv;
    const float4 gv = ((const float4*)(G  + (size_t)g * DIM))[tid];
    const float4 bv = ((const float4*)(Bn + (size_t)g * DIM))[tid];
    float2 y0, y1;
    y0.x = gv.x * (v.x - mu) * inv + bv.x;
    y0.y = gv.y * (v.y - mu) * inv + bv.y;
    y1.x = gv.z * (v.z - mu) * inv + bv.z;
    y1.y = gv.w * (v.w - mu) * inv + bv.w;
    __half2* dst = (__half2*)(g_ln + (size_t)r * DIM);
    dst[tid * 2 + 0] = __float22half2_rn(y0);
    dst[tid * 2 + 1] = __float22half2_rn(y1);
}

// ---------------------------------------------------------------------------
// K2/K3: fp16 mma.sync grouped GEMM, 128x128 tile, 256 threads, BK=64.
// Round-10 pipeline with the wait moved mid-body: CP_WAIT(1) after slices
// 0-2 drains only the stage issued a FULL body earlier; next-stage slice-0
// fragments are prefetched behind the barrier while slice-3 mma (already in
// registers) still runs. No exposed LDSM, no same-body load drain.
// ---------------------------------------------------------------------------
template<bool RELU, bool RESID, bool OUT_HALF>
__global__ __launch_bounds__(256, 2)
void mma_gemm(const __half* __restrict__ A, const __half* __restrict__ Bt,
              const float* __restrict__ bias, const float* __restrict__ resid,
              void* __restrict__ Cv, int N, int K) {
    extern __shared__ __half sm[];
    const int tid  = threadIdx.x;
    const int row0 = blockIdx.y * BM;
    const int col0 = blockIdx.x * BN;
    const int g    = g_dom[row0 >> 9];
    const __half* Bg = Bt + (size_t)g * N * K;

    const int lane  = tid & 31;
    const int wid   = tid >> 5;
    const int gid   = lane >> 2;
    const int tg    = lane & 3;
    const int warpm = wid & 1;        // m offset *64
    const int warpn = wid >> 1;       // n offset *32

    const uint32_t sm_base = smem_u32(sm);

    // ldmatrix lane offsets (bytes, relative to stage base); PADH=72 rows
    // (144 B) -> 8-row matrix hits 16*r mod 128 slots, conflict-free.
    const uint32_t aoff_b =
        (uint32_t)((warpm * 64 + (lane & 7) + ((lane >> 3) & 1) * 8) * PADH
                   + (lane >> 4) * 8) * 2u;
    const uint32_t boff_b =
        (uint32_t)(BM * PADH) * 2u +
        (uint32_t)((warpn * 32 + (lane & 7) + (lane >> 4) * 8) * PADH
                   + ((lane >> 3) & 1) * 8) * 2u;

    auto load_stage = [&](int kt, int s) {
        const int k0 = kt * BKK;
        __half* As = sm + s * STAGE_H;
        __half* Bs = As + BM * PADH;
        #pragma unroll
        for (int j = 0; j < 4; j++) {
            int c = tid + j * 256;
            int m = c >> 3, kc = (c & 7) << 3;
            cp_async16(&As[m * PADH + kc],
                       A + (size_t)(row0 + m) * K + k0 + kc);
        }
        #pragma unroll
        for (int j = 0; j < 4; j++) {
            int c = tid + j * 256;
            int n = c >> 3, kc = (c & 7) << 3;
            cp_async16(&Bs[n * PADH + kc],
                       Bg + (size_t)(col0 + n) * K + k0 + kc);
        }
        CP_COMMIT();
    };

    // fragment load for one k16 slice (ks in {0..3}) of stage at byte base
    auto frag_load = [&](uint32_t base, int ks, uint32_t a[4][4],
                         uint32_t b[4][2]) {
        const uint32_t Aaddr = base + aoff_b + (uint32_t)ks * 32u;
        const uint32_t Baddr = base + boff_b + (uint32_t)ks * 32u;
        #pragma unroll
        for (int mf = 0; mf < 4; mf++)
            ldsm_x4(a[mf][0], a[mf][1], a[mf][2], a[mf][3],
                    Aaddr + (uint32_t)(mf * 16 * PADH) * 2u);
        ldsm_x4(b[0][0], b[0][1], b[1][0], b[1][1], Baddr);
        ldsm_x4(b[2][0], b[2][1], b[3][0], b[3][1],
                Baddr + (uint32_t)(16 * PADH) * 2u);
    };

    float acc[4][4][4];
    #pragma unroll
    for (int i = 0; i < 4; i++)
        #pragma unroll
        for (int j = 0; j < 4; j++)
            #pragma unroll
            for (int q = 0; q < 4; q++) acc[i][j][q] = 0.f;

    const int KT = K / BKK;

    // prologue: issue stages 0,1; guarantee stage 0 resident (L1 may fly)
    load_stage(0, 0);
    load_stage(1, 1);
    CP_WAIT(1);
    __syncthreads();

    uint32_t a[2][4][4], b[2][4][2];
    int s_cur = 0;                 // slot of stage kt
    int s_ld  = NSTG - 1;          // slot for stage kt+2
    frag_load(sm_base, 0, a[0], b[0]);   // stage 0, slice 0

    for (int kt = 0; kt < KT; kt++) {
        // issue stage kt+2 into stage kt-1's slot (readers retired before
        // the barrier inside body kt-1); keep group cadence with an empty
        // commit in the tail so CP_WAIT(1) semantics stay aligned
        {
            int nx = kt + NSTG - 1;
            if (nx < KT) load_stage(nx, s_ld);
            else CP_COMMIT();
            if (++s_ld == NSTG) s_ld = 0;
        }
        const uint32_t base_cur = sm_base + (uint32_t)(s_cur * STAGE_H) * 2u;
        const int s_nxt = (s_cur + 1 == NSTG) ? 0 : s_cur + 1;
        const uint32_t base_nxt = sm_base + (uint32_t)(s_nxt * STAGE_H) * 2u;
        s_cur = s_nxt;

        // slices 0-2: prefetch ks+1 frags, mma ks
        #pragma unroll
        for (int ks = 0; ks < 3; ks++) {
            const int cb = ks & 1, nb = cb ^ 1;
            frag_load(base_cur, ks + 1, a[nb], b[nb]);
            #pragma unroll
            for (int mf = 0; mf < 4; mf++)
                #pragma unroll
                for (int nf = 0; nf < 4; nf++)
                    mma_f16(acc[mf][nf], a[cb][mf], b[cb][nf]);
        }

        // stage kt+1 was issued a full body ago: drain it (newest group,
        // L(kt+2)/dummy, stays in flight), barrier, prefetch its slice 0
        if (kt + 1 < KT) {
            CP_WAIT(1);
            __syncthreads();
            frag_load(base_nxt, 0, a[0], b[0]);
        }

        // slice 3 mma (fragments loaded during ks=2, in buffer 1)
        #pragma unroll
        for (int mf = 0; mf < 4; mf++)
            #pragma unroll
            for (int nf = 0; nf < 4; nf++)
                mma_f16(acc[mf][nf], a[1][mf], b[1][nf]);
    }

    // epilogue
    const float* biasg = bias + (size_t)g * N;
    #pragma unroll
    for (int mf = 0; mf < 4; mf++) {
        #pragma unroll
        for (int h = 0; h < 2; h++) {
            const int r = row0 + warpm * 64 + mf * 16 + gid + h * 8;
            const float* rrow = RESID ? (resid + (size_t)r * N) : nullptr;
            #pragma unroll
            for (int nf = 0; nf < 4; nf++) {
                const int cidx = col0 + warpn * 32 + nf * 8 + tg * 2;
                float2 v;
                v.x = acc[mf][nf][h * 2 + 0] + biasg[cidx];
                v.y = acc[mf][nf][h * 2 + 1] + biasg[cidx + 1];
                if (RELU) { v.x = fmaxf(v.x, 0.f); v.y = fmaxf(v.y, 0.f); }
                if (RESID) { v.x += rrow[cidx]; v.y += rrow[cidx + 1]; }
                if (OUT_HALF) {
                    __half2* crow = (__half2*)((__half*)Cv + (size_t)r * N + cidx);
                    *crow = __float22half2_rn(v);
                } else {
                    *(float2*)((float*)Cv + (size_t)r * N + cidx) = v;
                }
            }
        }
    }
}

// ---------------------------------------------------------------------------
extern "C" void kernel_launch(void* const* d_in, const int* in_sizes, int n_in,
                              void* d_out, int out_size) {
    const float* x   = (const float*)d_in[0];
    const int*   idx = (const int*)  d_in[1];
    const float* W1  = (const float*)d_in[2];
    const float* B1  = (const float*)d_in[3];
    const float* W2  = (const float*)d_in[4];
    const float* B2  = (const float*)d_in[5];
    const float* G   = (const float*)d_in[6];
    const float* Bn  = (const float*)d_in[7];
    float*       out = (float*)d_out;

    __half *ln_ptr, *h_ptr, *w1t_ptr, *w2t_ptr;
    cudaGetSymbolAddress((void**)&ln_ptr,  g_ln);
    cudaGetSymbolAddress((void**)&h_ptr,   g_h);
    cudaGetSymbolAddress((void**)&w1t_ptr, g_w1t);
    cudaGetSymbolAddress((void**)&w2t_ptr, g_w2t);

    static bool attr_done = false;
    if (!attr_done) {
        cudaFuncSetAttribute(mma_gemm<true, false, true>,
                             cudaFuncAttributeMaxDynamicSharedMemorySize, SMEM_BYTES);
        cudaFuncSetAttribute(mma_gemm<false, true, false>,
                             cudaFuncAttributeMaxDynamicSharedMemorySize, SMEM_BYTES);
        attr_done = true;
    }

    dom_kernel<<<1, 32>>>(idx);

    // fused: W1^T, W2^T, layernorm
    prep_kernel<<<PREP_GRID, 256>>>(W1, W2, x, G, Bn);

    // gemm1: h = relu(ln @ W1[g] + B1[g]) -> fp16   (KT = 16)
    mma_gemm<true, false, true><<<dim3(FFN / BN, NTOK / BM), 256, SMEM_BYTES>>>(
        ln_ptr, w1t_ptr, B1, nullptr, h_ptr, FFN, DIM);

    // gemm2: out = x + h @ W2[g] + B2[g] -> fp32    (KT = 32)
    mma_gemm<false, true, false><<<dim3(DIM / BN, NTOK / BM), 256, SMEM_BYTES>>>(
        h_ptr, w2t_ptr, B2, x, out, DIM, FFN);
}

// round 13
// speedup vs baseline: 1.1146x; 1.0202x over previous
#include <cuda_runtime.h>
#include <cuda_fp16.h>
#include <math.h>
#include <stdint.h>

// Problem constants
#define BATCH   32
#define SEQ     512
#define DIM     1024
#define FFN     2048
#define GDOM    4
#define NTOK    (BATCH * SEQ)
#define LN_EPS  1e-6f

// GEMM tiling: 128x128 CTA, BK=64 halves, 256 threads (8 warps, 2m x 4n)
#define BM 128
#define BN 128
#define BKK 64
#define NSTG 3
#define PADH 72                               // halves per k-row (64 data + 8 pad)
#define STAGE_H ((BM + BN) * PADH)            // 18432 halves = 36864 B per stage
#define SMEM_BYTES (NSTG * STAGE_H * 2)       // 110592

// ---------------------------------------------------------------------------
// Scratch (device globals; allocation-free per harness rules)
// ---------------------------------------------------------------------------
__device__ __half g_ln [(size_t)NTOK * DIM];        // 32 MB LN output (fp16)
__device__ __half g_h  [(size_t)NTOK * FFN];        // 64 MB hidden (fp16)
__device__ __half g_w1t[(size_t)GDOM * FFN * DIM];  // 16 MB W1^T [g][F][D]
__device__ __half g_w2t[(size_t)GDOM * DIM * FFN];  // 16 MB W2^T [g][D][F]
__device__ int    g_dom[BATCH];

// ---------------------------------------------------------------------------
// PTX helpers
// ---------------------------------------------------------------------------
__device__ __forceinline__ uint32_t smem_u32(const void* p) {
    uint32_t a;
    asm("{ .reg .u64 t; cvta.to.shared.u64 t, %1; cvt.u32.u64 %0, t; }"
        : "=r"(a) : "l"(p));
    return a;
}
__device__ __forceinline__ void cp_async16(void* s, const void* g) {
    uint32_t sa = smem_u32(s);
    asm volatile("cp.async.cg.shared.global [%0], [%1], 16;" :: "r"(sa), "l"(g));
}
#define CP_COMMIT() asm volatile("cp.async.commit_group;" ::: "memory")
#define CP_WAIT(n)  asm volatile("cp.async.wait_group %0;" :: "n"(n) : "memory")

__device__ __forceinline__ void ldsm_x4(uint32_t& r0, uint32_t& r1,
                                        uint32_t& r2, uint32_t& r3,
                                        uint32_t addr) {
    asm volatile("ldmatrix.sync.aligned.m8n8.x4.shared.b16 {%0,%1,%2,%3}, [%4];"
                 : "=r"(r0), "=r"(r1), "=r"(r2), "=r"(r3) : "r"(addr));
}

__device__ __forceinline__ void mma_f16(float* c, const uint32_t* a,
                                        const uint32_t* b) {
    asm volatile(
        "mma.sync.aligned.m16n8k16.row.col.f32.f16.f16.f32 "
        "{%0,%1,%2,%3}, {%4,%5,%6,%7}, {%8,%9}, {%0,%1,%2,%3};"
        : "+f"(c[0]), "+f"(c[1]), "+f"(c[2]), "+f"(c[3])
        : "r"(a[0]), "r"(a[1]), "r"(a[2]), "r"(a[3]), "r"(b[0]), "r"(b[1]));
}

// ---------------------------------------------------------------------------
// K0: batch -> domain
// ---------------------------------------------------------------------------
__global__ void dom_kernel(const int* __restrict__ idx) {
    int i = threadIdx.x;
    if (i < BATCH) g_dom[idx[i]] = i >> 3;
}

// ---------------------------------------------------------------------------
// K1 (fused prep): W1 transpose | W2 transpose | LayerNorm, role by blockIdx.
// Transpose: 64x64 tiles, float4 loads, uint4 (8xhalf) stores.
// ---------------------------------------------------------------------------
#define T_W1   (GDOM * (DIM / 64) * (FFN / 64))    // 2048
#define T_W2   (GDOM * (FFN / 64) * (DIM / 64))    // 2048
#define PREP_GRID (T_W1 + T_W2 + NTOK)             // 20480

__global__ __launch_bounds__(256)
void prep_kernel(const float* __restrict__ W1, const float* __restrict__ W2,
                 const float* __restrict__ x, const float* __restrict__ G,
                 const float* __restrict__ Bn) {
    __shared__ float tb[64][65];
    __shared__ float red_s[8], red_ss[8];
    __shared__ float s_mu, s_inv;

    const int bid = blockIdx.x;
    const int tid = threadIdx.x;

    if (bid < T_W1 + T_W2) {
        // ---- weight transpose role: W[g][R][C] fp32 -> Wt[g][C][R] fp16 ----
        const bool isw1 = bid < T_W1;
        const int id  = isw1 ? bid : bid - T_W1;
        const int R   = isw1 ? DIM : FFN;
        const int C   = isw1 ? FFN : DIM;
        const int ctiles = C / 64;
        const int g   = id / ((R / 64) * ctiles);
        const int rem = id % ((R / 64) * ctiles);
        const int cy  = rem / ctiles;        // row tile
        const int cx  = rem % ctiles;        // col tile
        const float* Wg  = (isw1 ? W1 : W2) + (size_t)g * R * C;
        __half*      Wtg = (isw1 ? g_w1t : g_w2t) + (size_t)g * R * C;
        const int r0 = cy * 64, c0 = cx * 64;

        // load 64x64 floats: 1024 float4, 4 per thread
        #pragma unroll
        for (int i = 0; i < 4; i++) {
            int idx2 = tid + i * 256;
            int fr  = idx2 >> 4;          // 0..63
            int fc4 = idx2 & 15;          // float4 column group
            float4 v = *(const float4*)(Wg + (size_t)(r0 + fr) * C + c0 + fc4 * 4);
            tb[fr][fc4 * 4 + 0] = v.x;
            tb[fr][fc4 * 4 + 1] = v.y;
            tb[fr][fc4 * 4 + 2] = v.z;
            tb[fr][fc4 * 4 + 3] = v.w;
        }
        __syncthreads();

        // store transposed as fp16: 512 uint4 (8 halves), 2 per thread
        #pragma unroll
        for (int i = 0; i < 2; i++) {
            int idx2 = tid + i * 256;
            int oc = idx2 >> 3;           // 0..63 (C index within tile)
            int og = idx2 & 7;            // 8-half group along R
            __half hv[8];
            #pragma unroll
            for (int j = 0; j < 8; j++)
                hv[j] = __float2half_rn(tb[og * 8 + j][oc]);
            *(uint4*)(Wtg + (size_t)(c0 + oc) * R + r0 + og * 8) =
                *(const uint4*)hv;
        }
        return;
    }

    // ---- layernorm role ----
    const int r = bid - (T_W1 + T_W2);
    const int g = g_dom[r >> 9];

    const float4 v = ((const float4*)(x + (size_t)r * DIM))[tid];
    float s  = v.x + v.y + v.z + v.w;
    float ss = v.x * v.x + v.y * v.y + v.z * v.z + v.w * v.w;
    #pragma unroll
    for (int o = 16; o > 0; o >>= 1) {
        s  += __shfl_down_sync(0xffffffffu, s,  o);
        ss += __shfl_down_sync(0xffffffffu, ss, o);
    }
    if ((tid & 31) == 0) { red_s[tid >> 5] = s; red_ss[tid >> 5] = ss; }
    __syncthreads();
    if (tid == 0) {
        float ts = 0.f, tss = 0.f;
        #pragma unroll
        for (int i = 0; i < 8; i++) { ts += red_s[i]; tss += red_ss[i]; }
        float mu  = ts * (1.0f / DIM);
        float var = (tss - (float)DIM * mu * mu) * (1.0f / (DIM - 1));
        var = fmaxf(var, 0.0f);
        s_mu  = mu;
        s_inv = 1.0f / (sqrtf(var) + LN_EPS);
    }
    __syncthreads();
    const float mu = s_mu, inv = s_inv;
    const float4 gv = ((const float4*)(G  + (size_t)g * DIM))[tid];
    const float4 bv = ((const float4*)(Bn + (size_t)g * DIM))[tid];
    float2 y0, y1;
    y0.x = gv.x * (v.x - mu) * inv + bv.x;
    y0.y = gv.y * (v.y - mu) * inv + bv.y;
    y1.x = gv.z * (v.z - mu) * inv + bv.z;
    y1.y = gv.w * (v.w - mu) * inv + bv.w;
    __half2* dst = (__half2*)(g_ln + (size_t)r * DIM);
    dst[tid * 2 + 0] = __float22half2_rn(y0);
    dst[tid * 2 + 1] = __float22half2_rn(y1);
}

// ---------------------------------------------------------------------------
// K2/K3: fp16 mma.sync grouped GEMM, 128x128 tile, 256 threads, BK=64.
// (Mainloop identical to the round-12 best: mid-body CP_WAIT(1), register
// ping-pong fragments, no exposed LDSM.)
// ---------------------------------------------------------------------------
template<bool RELU, bool RESID, bool OUT_HALF>
__global__ __launch_bounds__(256, 2)
void mma_gemm(const __half* __restrict__ A, const __half* __restrict__ Bt,
              const float* __restrict__ bias, const float* __restrict__ resid,
              void* __restrict__ Cv, int N, int K) {
    extern __shared__ __half sm[];
    const int tid  = threadIdx.x;
    const int row0 = blockIdx.y * BM;
    const int col0 = blockIdx.x * BN;
    const int g    = g_dom[row0 >> 9];
    const __half* Bg = Bt + (size_t)g * N * K;

    const int lane  = tid & 31;
    const int wid   = tid >> 5;
    const int gid   = lane >> 2;
    const int tg    = lane & 3;
    const int warpm = wid & 1;        // m offset *64
    const int warpn = wid >> 1;       // n offset *32

    const uint32_t sm_base = smem_u32(sm);

    const uint32_t aoff_b =
        (uint32_t)((warpm * 64 + (lane & 7) + ((lane >> 3) & 1) * 8) * PADH
                   + (lane >> 4) * 8) * 2u;
    const uint32_t boff_b =
        (uint32_t)(BM * PADH) * 2u +
        (uint32_t)((warpn * 32 + (lane & 7) + (lane >> 4) * 8) * PADH
                   + ((lane >> 3) & 1) * 8) * 2u;

    auto load_stage = [&](int kt, int s) {
        const int k0 = kt * BKK;
        __half* As = sm + s * STAGE_H;
        __half* Bs = As + BM * PADH;
        #pragma unroll
        for (int j = 0; j < 4; j++) {
            int c = tid + j * 256;
            int m = c >> 3, kc = (c & 7) << 3;
            cp_async16(&As[m * PADH + kc],
                       A + (size_t)(row0 + m) * K + k0 + kc);
        }
        #pragma unroll
        for (int j = 0; j < 4; j++) {
            int c = tid + j * 256;
            int n = c >> 3, kc = (c & 7) << 3;
            cp_async16(&Bs[n * PADH + kc],
                       Bg + (size_t)(col0 + n) * K + k0 + kc);
        }
        CP_COMMIT();
    };

    auto frag_load = [&](uint32_t base, int ks, uint32_t a[4][4],
                         uint32_t b[4][2]) {
        const uint32_t Aaddr = base + aoff_b + (uint32_t)ks * 32u;
        const uint32_t Baddr = base + boff_b + (uint32_t)ks * 32u;
        #pragma unroll
        for (int mf = 0; mf < 4; mf++)
            ldsm_x4(a[mf][0], a[mf][1], a[mf][2], a[mf][3],
                    Aaddr + (uint32_t)(mf * 16 * PADH) * 2u);
        ldsm_x4(b[0][0], b[0][1], b[1][0], b[1][1], Baddr);
        ldsm_x4(b[2][0], b[2][1], b[3][0], b[3][1],
                Baddr + (uint32_t)(16 * PADH) * 2u);
    };

    float acc[4][4][4];
    #pragma unroll
    for (int i = 0; i < 4; i++)
        #pragma unroll
        for (int j = 0; j < 4; j++)
            #pragma unroll
            for (int q = 0; q < 4; q++) acc[i][j][q] = 0.f;

    const int KT = K / BKK;

    load_stage(0, 0);
    load_stage(1, 1);
    CP_WAIT(1);
    __syncthreads();

    uint32_t a[2][4][4], b[2][4][2];
    int s_cur = 0;
    int s_ld  = NSTG - 1;
    frag_load(sm_base, 0, a[0], b[0]);

    for (int kt = 0; kt < KT; kt++) {
        {
            int nx = kt + NSTG - 1;
            if (nx < KT) load_stage(nx, s_ld);
            else CP_COMMIT();
            if (++s_ld == NSTG) s_ld = 0;
        }
        const uint32_t base_cur = sm_base + (uint32_t)(s_cur * STAGE_H) * 2u;
        const int s_nxt = (s_cur + 1 == NSTG) ? 0 : s_cur + 1;
        const uint32_t base_nxt = sm_base + (uint32_t)(s_nxt * STAGE_H) * 2u;
        s_cur = s_nxt;

        #pragma unroll
        for (int ks = 0; ks < 3; ks++) {
            const int cb = ks & 1, nb = cb ^ 1;
            frag_load(base_cur, ks + 1, a[nb], b[nb]);
            #pragma unroll
            for (int mf = 0; mf < 4; mf++)
                #pragma unroll
                for (int nf = 0; nf < 4; nf++)
                    mma_f16(acc[mf][nf], a[cb][mf], b[cb][nf]);
        }

        if (kt + 1 < KT) {
            CP_WAIT(1);
            __syncthreads();
            frag_load(base_nxt, 0, a[0], b[0]);
        }

        #pragma unroll
        for (int mf = 0; mf < 4; mf++)
            #pragma unroll
            for (int nf = 0; nf < 4; nf++)
                mma_f16(acc[mf][nf], a[1][mf], b[1][nf]);
    }

    // epilogue (bias via float2)
    const float* biasg = bias + (size_t)g * N;
    #pragma unroll
    for (int mf = 0; mf < 4; mf++) {
        #pragma unroll
        for (int h = 0; h < 2; h++) {
            const int r = row0 + warpm * 64 + mf * 16 + gid + h * 8;
            const float* rrow = RESID ? (resid + (size_t)r * N) : nullptr;
            #pragma unroll
            for (int nf = 0; nf < 4; nf++) {
                const int cidx = col0 + warpn * 32 + nf * 8 + tg * 2;
                const float2 bb = *(const float2*)(biasg + cidx);
                float2 v;
                v.x = acc[mf][nf][h * 2 + 0] + bb.x;
                v.y = acc[mf][nf][h * 2 + 1] + bb.y;
                if (RELU) { v.x = fmaxf(v.x, 0.f); v.y = fmaxf(v.y, 0.f); }
                if (RESID) {
                    const float2 xv = *(const float2*)(rrow + cidx);
                    v.x += xv.x; v.y += xv.y;
                }
                if (OUT_HALF) {
                    __half2* crow = (__half2*)((__half*)Cv + (size_t)r * N + cidx);
                    *crow = __float22half2_rn(v);
                } else {
                    *(float2*)((float*)Cv + (size_t)r * N + cidx) = v;
                }
            }
        }
    }
}

// ---------------------------------------------------------------------------
extern "C" void kernel_launch(void* const* d_in, const int* in_sizes, int n_in,
                              void* d_out, int out_size) {
    const float* x   = (const float*)d_in[0];
    const int*   idx = (const int*)  d_in[1];
    const float* W1  = (const float*)d_in[2];
    const float* B1  = (const float*)d_in[3];
    const float* W2  = (const float*)d_in[4];
    const float* B2  = (const float*)d_in[5];
    const float* G   = (const float*)d_in[6];
    const float* Bn  = (const float*)d_in[7];
    float*       out = (float*)d_out;

    __half *ln_ptr, *h_ptr, *w1t_ptr, *w2t_ptr;
    cudaGetSymbolAddress((void**)&ln_ptr,  g_ln);
    cudaGetSymbolAddress((void**)&h_ptr,   g_h);
    cudaGetSymbolAddress((void**)&w1t_ptr, g_w1t);
    cudaGetSymbolAddress((void**)&w2t_ptr, g_w2t);

    static bool attr_done = false;
    if (!attr_done) {
        cudaFuncSetAttribute(mma_gemm<true, false, true>,
                             cudaFuncAttributeMaxDynamicSharedMemorySize, SMEM_BYTES);
        cudaFuncSetAttribute(mma_gemm<false, true, false>,
                             cudaFuncAttributeMaxDynamicSharedMemorySize, SMEM_BYTES);
        attr_done = true;
    }

    dom_kernel<<<1, 32>>>(idx);

    // fused: W1^T, W2^T, layernorm
    prep_kernel<<<PREP_GRID, 256>>>(W1, W2, x, G, Bn);

    // gemm1: h = relu(ln @ W1[g] + B1[g]) -> fp16   (KT = 16)
    mma_gemm<true, false, true><<<dim3(FFN / BN, NTOK / BM), 256, SMEM_BYTES>>>(
        ln_ptr, w1t_ptr, B1, nullptr, h_ptr, FFN, DIM);

    // gemm2: out = x + h @ W2[g] + B2[g] -> fp32    (KT = 32)
    mma_gemm<false, true, false><<<dim3(DIM / BN, NTOK / BM), 256, SMEM_BYTES>>>(
        h_ptr, w2t_ptr, B2, x, out, DIM, FFN);
}